// round 15
// baseline (speedup 1.0000x reference)
#include <cuda_runtime.h>
#include <cuda_bf16.h>
#include <math.h>
#include <stdint.h>

#define EPSV 1e-5f
#define BB 2
#define CC 256
#define C8 32
#define NP 4096          // 16*16*16 positions
#define PADN 5832        // 18*18*18
#define KCONV (CC*27)    // 6912

// ---------------- scratch ----------------
__device__ float g_pad[BB*CC*PADN];
__device__ float g_y[BB*CC*NP];
__device__ float g_out[BB*CC*NP];
__device__ float g_q[BB*C8*NP];
__device__ float g_k[BB*C8*NP];
__device__ __nv_bfloat16 g_vh[BB*CC*NP];
__device__ __nv_bfloat16 g_attnh[(size_t)BB*NP*NP];
__device__ float g_wt[CC*KCONV];
__device__ float g_wt2[CC*KCONV];

// padded-offset per conv tap (strides 324/18/1)
__constant__ int c_doff[27] = {
  -343,-342,-341,-325,-324,-323,-307,-306,-305,
   -19, -18, -17,  -1,   0,   1,  17,  18,  19,
   305, 306, 307, 323, 324, 325, 341, 342, 343};

// ---------------- helpers ----------------
__device__ __forceinline__ float tf32r(float x) {
    uint32_t u;
    asm("cvt.rna.tf32.f32 %0, %1;" : "=r"(u) : "f"(x));
    return __uint_as_float(u);
}
__device__ __forceinline__ void mma_tf32(float (&d)[4], const float4 &a, const float2 &b) {
    asm volatile(
        "mma.sync.aligned.m16n8k8.row.col.f32.tf32.tf32.f32 "
        "{%0,%1,%2,%3}, {%4,%5,%6,%7}, {%8,%9}, {%0,%1,%2,%3};\n"
        : "+f"(d[0]), "+f"(d[1]), "+f"(d[2]), "+f"(d[3])
        : "r"(__float_as_uint(a.x)), "r"(__float_as_uint(a.y)),
          "r"(__float_as_uint(a.z)), "r"(__float_as_uint(a.w)),
          "r"(__float_as_uint(b.x)), "r"(__float_as_uint(b.y)));
}
__device__ __forceinline__ void mma_bf16(float (&d)[4], const uint4 &a, const uint2 &b) {
    asm volatile(
        "mma.sync.aligned.m16n8k16.row.col.f32.bf16.bf16.f32 "
        "{%0,%1,%2,%3}, {%4,%5,%6,%7}, {%8,%9}, {%0,%1,%2,%3};\n"
        : "+f"(d[0]), "+f"(d[1]), "+f"(d[2]), "+f"(d[3])
        : "r"(a.x), "r"(a.y), "r"(a.z), "r"(a.w), "r"(b.x), "r"(b.y));
}
__device__ __forceinline__ uint32_t pbf2(float lo, float hi) {
    return (uint32_t)__bfloat16_as_ushort(__float2bfloat16_rn(lo))
         | ((uint32_t)__bfloat16_as_ushort(__float2bfloat16_rn(hi)) << 16);
}

// ---------------- weight transpose (both weights in one launch) ----------------
__global__ __launch_bounds__(256) void wtrans_kernel(const float* __restrict__ w1,
                                                     const float* __restrict__ w2) {
    int co = blockIdx.x;
    int cin = threadIdx.x;
    const float* w   = blockIdx.y ? w2 : w1;
    float*       wt  = blockIdx.y ? g_wt2 : g_wt;
    const float* src = w + (size_t)co * KCONV + (size_t)cin * 27;
    float v[27];
    #pragma unroll
    for (int t = 0; t < 27; t++) v[t] = src[t];
    float* dst = wt + (size_t)co * KCONV + cin;
    #pragma unroll
    for (int t = 0; t < 27; t++) dst[t * 256] = v[t];
}

// ---------------- pad kernel: x -> g_pad ----------------
__global__ void pad_kernel(const float* __restrict__ x) {
    int bc = blockIdx.x;
    const float* src = x + (size_t)bc * NP;
    float* dst = g_pad + (size_t)bc * PADN;
    int tid = threadIdx.x;
    float4 z4 = make_float4(0.f, 0.f, 0.f, 0.f);
    #pragma unroll
    for (int s = 0; s < 6; s++) {
        int i = tid + s * 256;
        if (i < PADN / 4) *(float4*)(dst + i * 4) = z4;
    }
    __syncthreads();
    #pragma unroll
    for (int s = 0; s < 16; s++) {
        int idx = tid + s * 256;
        int zc = idx & 15, yc = (idx >> 4) & 15, xc = idx >> 8;
        dst[(xc + 1) * 324 + (yc + 1) * 18 + (zc + 1)] = src[idx];
    }
}

// ---------------- block-wide mean/rstd ----------------
__device__ __forceinline__ void block_stats(const float* __restrict__ src,
                                            float& mean, float& rstd) {
    float s = 0.f, ss = 0.f;
    const float4* s4 = (const float4*)src;
    #pragma unroll
    for (int i = threadIdx.x; i < NP / 4; i += 256) {
        float4 v = s4[i];
        s  += v.x + v.y + v.z + v.w;
        ss += v.x * v.x + v.y * v.y + v.z * v.z + v.w * v.w;
    }
    #pragma unroll
    for (int o = 16; o; o >>= 1) {
        s  += __shfl_down_sync(0xffffffffu, s, o);
        ss += __shfl_down_sync(0xffffffffu, ss, o);
    }
    __shared__ float sh_s[8], sh_ss[8], sh_m, sh_r;
    int w = threadIdx.x >> 5, l = threadIdx.x & 31;
    if (l == 0) { sh_s[w] = s; sh_ss[w] = ss; }
    __syncthreads();
    if (threadIdx.x == 0) {
        float S = 0.f, SS = 0.f;
        #pragma unroll
        for (int i = 0; i < 8; i++) { S += sh_s[i]; SS += sh_ss[i]; }
        float m = S * (1.0f / NP);
        float var = SS * (1.0f / NP) - m * m;
        sh_m = m;
        sh_r = rsqrtf(var + EPSV);
    }
    __syncthreads();
    mean = sh_m; rstd = sh_r;
}

// ---------------- fused: stats then instnorm+relu -> g_pad ----------------
__global__ void stats_pad_kernel() {
    int bc = blockIdx.x;
    const float* src = g_y + (size_t)bc * NP;
    float m, r;
    block_stats(src, m, r);
    float* dst = g_pad + (size_t)bc * PADN;
    int tid = threadIdx.x;
    float4 z4 = make_float4(0.f, 0.f, 0.f, 0.f);
    #pragma unroll
    for (int s = 0; s < 6; s++) {
        int i = tid + s * 256;
        if (i < PADN / 4) *(float4*)(dst + i * 4) = z4;
    }
    __syncthreads();
    #pragma unroll
    for (int s = 0; s < 16; s++) {
        int idx = tid + s * 256;
        int zc = idx & 15, yc = (idx >> 4) & 15, xc = idx >> 8;
        dst[(xc + 1) * 324 + (yc + 1) * 18 + (zc + 1)] = fmaxf((src[idx] - m) * r, 0.f);
    }
}

// ---------------- fused: stats then g_out = x + instnorm(g_y) ----------------
__global__ void stats_norm_kernel(const float* __restrict__ x) {
    int bc = blockIdx.x;
    const float* src = g_y + (size_t)bc * NP;
    float m, r;
    block_stats(src, m, r);
    const float4* x4 = (const float4*)(x + (size_t)bc * NP);
    const float4* y4 = (const float4*)src;
    float4* d4 = (float4*)(g_out + (size_t)bc * NP);
    #pragma unroll
    for (int i = threadIdx.x; i < NP / 4; i += 256) {
        float4 a = x4[i], b = y4[i];
        d4[i] = make_float4(a.x + (b.x - m) * r, a.y + (b.y - m) * r,
                            a.z + (b.z - m) * r, a.w + (b.w - m) * r);
    }
}

// ============================================================================
// Pipelined mma.sync tf32 GEMM — 512 threads (16 warps), 128x128 tile, k32,
// 2-stage smem. Warp grid 4x4, warp tile 32x32 (acc[2][4][4]).
// MODE 0 (CONV):   A=wt[co][(tap,cin)],  B=im2col(g_pad), dst=g_y fp32 (+bias)
// MODE 1 (VPROJ):  A=Aext(wv),           B=g_out[c][p],   dst=g_vh bf16 (+bias)
// MODE 2 (ENERGY): A=q^T strided, B=k strided, KTOT=32,   dst=g_attnh bf16
// ============================================================================
#define STG_FLOATS 8320
#define SMEM_DYN (2 * STG_FLOATS * 4)

template<int MODE, int KTOT, int CONVSEL>
__global__ __launch_bounds__(512, 1)
void tc_gemm(const float* __restrict__ Aext, const float* __restrict__ bias) {
    constexpr int NCH = KTOT / 32;
    extern __shared__ float sm[];
    const int tid = threadIdx.x, wid = tid >> 5, lane = tid & 31;
    const int bb = blockIdx.z;
    const int m0 = blockIdx.y * 128, n0 = blockIdx.x * 128;

    // ---- A loader: amt(8) x arg(8) x akb(4) x ahf(2) = 512 threads ----
    const int amt = tid >> 6;
    const int arg = (tid >> 3) & 7;
    const int akb = (tid >> 1) & 3;
    const int ac0 = (tid & 1) * 2;       // c in {ac0, ac0+1}
    const float* aptr0 = nullptr;
    const float* aptr1 = nullptr;
    const float* aqbase = nullptr;
    {
        int m = m0 + amt * 16 + arg;
        if (MODE == 2) {
            aqbase = g_q + (size_t)bb * C8 * NP + m;
        } else {
            const float* base = (MODE == 0) ? (CONVSEL ? g_wt2 : g_wt) : Aext;
            aptr0 = base + (size_t)m * KTOT + akb * 8;
            aptr1 = base + (size_t)(m + 8) * KTOT + akb * 8;
        }
    }

    // ---- B loader: bn(128) x bkb(4) = 512 threads ----
    const int bn = tid >> 2;
    const int bkb1 = tid & 3;            // k-block (8 k) within 32
    int pofs = 0;
    const float* bbase = nullptr;
    if (MODE == 0) {
        int p = n0 + bn;
        int pz = p & 15, py = (p >> 4) & 15, px = p >> 8;
        pofs = (px + 1) * 324 + (py + 1) * 18 + (pz + 1);
        bbase = g_pad + (size_t)bb * CC * PADN;
    } else if (MODE == 1) {
        bbase = g_out + (size_t)bb * CC * NP + n0 + bn;
    } else {
        bbase = g_k + (size_t)bb * C8 * NP + n0 + bn;
    }

    float ar0[8], ar1[8], br[8];

    #define LOAD_A(ch_) do { \
        if (MODE == 2) { \
            _Pragma("unroll") \
            for (int t = 0; t < 2; t++) { \
                int c = ac0 + t; \
                size_t o0 = (size_t)((ch_) * 32 + akb * 8 + c) * NP; \
                size_t o1 = (size_t)((ch_) * 32 + akb * 8 + c + 4) * NP; \
                ar0[c] = aqbase[o0];     ar1[c] = aqbase[o0 + 8]; \
                ar0[c + 4] = aqbase[o1]; ar1[c + 4] = aqbase[o1 + 8]; \
            } \
        } else { \
            *(float2*)(ar0 + ac0)     = *(const float2*)(aptr0 + (size_t)(ch_) * 32 + ac0); \
            *(float2*)(ar0 + ac0 + 4) = *(const float2*)(aptr0 + (size_t)(ch_) * 32 + ac0 + 4); \
            *(float2*)(ar1 + ac0)     = *(const float2*)(aptr1 + (size_t)(ch_) * 32 + ac0); \
            *(float2*)(ar1 + ac0 + 4) = *(const float2*)(aptr1 + (size_t)(ch_) * 32 + ac0 + 4); \
        } \
    } while (0)

    #define LOAD_B(ch_) do { \
        if (MODE == 0) { \
            _Pragma("unroll") \
            for (int c = 0; c < 8; c++) { \
                int k = (ch_) * 32 + bkb1 * 8 + c; \
                int tap = k >> 8, cin = k & 255; \
                br[c] = bbase[(size_t)cin * PADN + c_doff[tap] + pofs]; \
            } \
        } else { \
            _Pragma("unroll") \
            for (int c = 0; c < 8; c++) { \
                int k = (ch_) * 32 + bkb1 * 8 + c; \
                br[c] = bbase[(size_t)k * NP]; \
            } \
        } \
    } while (0)

    #define STORE_AB(stg_) do { \
        float* As_ = sm + (stg_) * STG_FLOATS + amt * 512 + akb * 128 + arg * 16; \
        _Pragma("unroll") \
        for (int t = 0; t < 2; t++) { \
            int c = ac0 + t; \
            *(float4*)(As_ + c * 4) = make_float4( \
                tf32r(ar0[c]), tf32r(ar1[c]), tf32r(ar0[c + 4]), tf32r(ar1[c + 4])); \
        } \
        float* Bs_ = sm + (stg_) * STG_FLOATS + 4096 + (bn >> 3) * 264 + (bn & 7) * 8; \
        _Pragma("unroll") \
        for (int c = 0; c < 4; c++) { \
            *(float2*)(Bs_ + bkb1 * 64 + c * 2) = \
                make_float2(tf32r(br[c]), tf32r(br[c + 4])); \
        } \
    } while (0)

    const int wm = wid & 3, wn = wid >> 2;   // 4x4 warp grid, warp tile 32x32
    float acc[2][4][4];
    #pragma unroll
    for (int i = 0; i < 2; i++)
        #pragma unroll
        for (int j = 0; j < 4; j++)
            #pragma unroll
            for (int k = 0; k < 4; k++) acc[i][j][k] = 0.f;

    LOAD_A(0); LOAD_B(0);
    STORE_AB(0);
    if (NCH > 1) { LOAD_A(1); LOAD_B(1); }
    __syncthreads();

    for (int ch = 0; ch < NCH; ch++) {
        int cur = ch & 1;
        if (ch + 1 < NCH) STORE_AB(cur ^ 1);
        if (ch + 2 < NCH) { LOAD_A(ch + 2); LOAD_B(ch + 2); }

        const float* As_ = sm + cur * STG_FLOATS;
        const float* Bs_ = As_ + 4096;
        #pragma unroll
        for (int kb = 0; kb < 4; kb++) {
            float4 af[2]; float2 bf[4];
            #pragma unroll
            for (int mt = 0; mt < 2; mt++)
                af[mt] = *(const float4*)(As_ + (wm * 2 + mt) * 512 + kb * 128 + lane * 4);
            #pragma unroll
            for (int nt = 0; nt < 4; nt++)
                bf[nt] = *(const float2*)(Bs_ + (wn * 4 + nt) * 264 + kb * 64 + lane * 2);
            #pragma unroll
            for (int mt = 0; mt < 2; mt++)
                #pragma unroll
                for (int nt = 0; nt < 4; nt++)
                    mma_tf32(acc[mt][nt], af[mt], bf[nt]);
        }
        __syncthreads();
    }

    #undef LOAD_A
    #undef LOAD_B
    #undef STORE_AB

    const int g = lane >> 2, tg = lane & 3;
    #pragma unroll
    for (int mt = 0; mt < 2; mt++) {
        int m = m0 + wm * 32 + mt * 16 + g;
        float bs0 = 0.f, bs1 = 0.f;
        if (MODE != 2) { bs0 = bias[m]; bs1 = bias[m + 8]; }
        #pragma unroll
        for (int nt = 0; nt < 4; nt++) {
            int n = n0 + wn * 32 + nt * 8 + tg * 2;
            if (MODE == 0) {
                size_t base0 = (size_t)(bb * CC + m) * NP + n;
                size_t base1 = base0 + (size_t)8 * NP;
                *(float2*)(g_y + base0) = make_float2(acc[mt][nt][0] + bs0, acc[mt][nt][1] + bs0);
                *(float2*)(g_y + base1) = make_float2(acc[mt][nt][2] + bs1, acc[mt][nt][3] + bs1);
            } else if (MODE == 1) {
                size_t base0 = (size_t)(bb * CC + m) * NP + n;
                size_t base1 = base0 + (size_t)8 * NP;
                *(uint32_t*)(g_vh + base0) = pbf2(acc[mt][nt][0] + bs0, acc[mt][nt][1] + bs0);
                *(uint32_t*)(g_vh + base1) = pbf2(acc[mt][nt][2] + bs1, acc[mt][nt][3] + bs1);
            } else {
                size_t base0 = ((size_t)bb * NP + m) * NP + n;
                size_t base1 = base0 + (size_t)8 * NP;
                *(uint32_t*)(g_attnh + base0) = pbf2(acc[mt][nt][0], acc[mt][nt][1]);
                *(uint32_t*)(g_attnh + base1) = pbf2(acc[mt][nt][2], acc[mt][nt][3]);
            }
        }
    }
}

// ============================================================================
// o-GEMM, bf16 m16n8k16 (unchanged 256-thread version)
// ============================================================================
#define OA_U32 2048
#define OB_U32 (16*136)
#define OSTG_U32 (OA_U32 + OB_U32)
#define OSMEM (2 * OSTG_U32 * 4)

__global__ __launch_bounds__(256, 1)
void o_gemm_bf16(const float* __restrict__ gamma, float* __restrict__ dout) {
    extern __shared__ uint32_t smu[];
    const int tid = threadIdx.x, wid = tid >> 5, lane = tid & 31;
    const int bb = blockIdx.z, m0 = blockIdx.y * 128, i0 = blockIdx.x * 128;
    const int wm = wid & 1, wn = wid >> 1;

    const uint32_t *av0 = nullptr, *av1 = nullptr;
    uint32_t aoff = 0;
    if (tid < 128) {
        int rpi = tid >> 1, akb = tid & 1;
        int mt = rpi >> 3, rp = rpi & 7;
        int m = m0 + mt * 16 + rp;
        av0 = (const uint32_t*)(g_vh + (size_t)(bb * CC + m) * NP) + akb * 8;
        av1 = av0 + (size_t)4 * NP;
        aoff = mt * 256 + akb * 128 + rp * 16;
    }
    const int bn = tid >> 1, bkb = tid & 1;
    const __nv_bfloat16* bptr = g_attnh + ((size_t)bb * NP + i0 + bn) * NP + bkb * 16;
    const uint32_t boff = OA_U32 + (bn >> 3) * 136 + bkb * 68 + (bn & 7) * 8;

    uint32_t a0u[8], a1u[8];
    uint32_t brg[8];

    #define OLOAD(ch_) do { \
        if (tid < 128) { \
            *(uint4*)(a0u)     = *(const uint4*)(av0 + (size_t)(ch_) * 16); \
            *(uint4*)(a0u + 4) = *(const uint4*)(av0 + (size_t)(ch_) * 16 + 4); \
            *(uint4*)(a1u)     = *(const uint4*)(av1 + (size_t)(ch_) * 16); \
            *(uint4*)(a1u + 4) = *(const uint4*)(av1 + (size_t)(ch_) * 16 + 4); \
        } \
        *(uint4*)(brg)     = *(const uint4*)(bptr + (size_t)(ch_) * 32); \
        *(uint4*)(brg + 4) = *(const uint4*)(bptr + (size_t)(ch_) * 32 + 8); \
    } while (0)

    #define OSTORE(stg_) do { \
        uint32_t* s_ = smu + (stg_) * OSTG_U32; \
        if (tid < 128) { \
            _Pragma("unroll") \
            for (int t = 0; t < 4; t++) { \
                *(uint4*)(s_ + aoff + t * 4) = \
                    make_uint4(a0u[t], a1u[t], a0u[t + 4], a1u[t + 4]); \
            } \
        } \
        _Pragma("unroll") \
        for (int t = 0; t < 4; t++) \
            *(uint2*)(s_ + boff + t * 2) = make_uint2(brg[t], brg[t + 4]); \
    } while (0)

    float acc[4][4][4];
    #pragma unroll
    for (int i = 0; i < 4; i++)
        #pragma unroll
        for (int j = 0; j < 4; j++)
            #pragma unroll
            for (int k = 0; k < 4; k++) acc[i][j][k] = 0.f;

    OLOAD(0); OSTORE(0); OLOAD(1);
    __syncthreads();

    constexpr int NCH = NP / 32;   // 128
    for (int ch = 0; ch < NCH; ch++) {
        int cur = ch & 1;
        if (ch + 1 < NCH) OSTORE(cur ^ 1);
        if (ch + 2 < NCH) OLOAD(ch + 2);

        const uint32_t* s_ = smu + cur * OSTG_U32;
        #pragma unroll
        for (int kb = 0; kb < 2; kb++) {
            uint4 af[4]; uint2 bf[4];
            #pragma unroll
            for (int mt = 0; mt < 4; mt++)
                af[mt] = *(const uint4*)(s_ + (wm * 4 + mt) * 256 + kb * 128 + lane * 4);
            #pragma unroll
            for (int nt = 0; nt < 4; nt++)
                bf[nt] = *(const uint2*)(s_ + OA_U32 + (wn * 4 + nt) * 136 + kb * 68 + lane * 2);
            #pragma unroll
            for (int mt = 0; mt < 4; mt++)
                #pragma unroll
                for (int nt = 0; nt < 4; nt++)
                    mma_bf16(acc[mt][nt], af[mt], bf[nt]);
        }
        __syncthreads();
    }

    #undef OLOAD
    #undef OSTORE

    const int g = lane >> 2, tg = lane & 3;
    const float gm = gamma[0];
    #pragma unroll
    for (int mt = 0; mt < 4; mt++) {
        int m = m0 + wm * 64 + mt * 16 + g;
        #pragma unroll
        for (int nt = 0; nt < 4; nt++) {
            int n = i0 + wn * 32 + nt * 8 + tg * 2;
            size_t base0 = (size_t)(bb * CC + m) * NP + n;
            size_t base1 = base0 + (size_t)8 * NP;
            const float* r0 = g_out + base0;
            const float* r1 = g_out + base1;
            *(float2*)(dout + base0) =
                make_float2(gm * acc[mt][nt][0] + r0[0], gm * acc[mt][nt][1] + r0[1]);
            *(float2*)(dout + base1) =
                make_float2(gm * acc[mt][nt][2] + r1[0], gm * acc[mt][nt][3] + r1[1]);
        }
    }
}

// ---------------- q and k projections fused (FFMA, small) ----------------
__global__ __launch_bounds__(256) void qk_gemm(const float* __restrict__ wq, const float* __restrict__ bq,
                                               const float* __restrict__ wk, const float* __restrict__ bk) {
    __shared__ float As[8][64];
    __shared__ float Bs[8][128];
    int tid = threadIdx.x, b = blockIdx.z;
    int p0 = blockIdx.x * 128;
    int arow = tid >> 2;
    int acol = (tid & 3) * 2;
    const float* ap = ((arow < 32) ? (wq + arow * CC) : (wk + (arow - 32) * CC)) + acol;
    int brow = tid >> 5, bcol = (tid & 31) * 4;
    const float* bp = g_out + (b * CC + brow) * NP + p0 + bcol;
    int ty = tid >> 4, tx = tid & 15;
    float acc[4][8];
    #pragma unroll
    for (int i = 0; i < 4; i++)
        #pragma unroll
        for (int j = 0; j < 8; j++) acc[i][j] = 0.f;

    for (int it = 0; it < CC / 8; ++it) {
        float2 av = *(const float2*)(ap + it * 8);
        float4 bv = *(const float4*)(bp + (size_t)it * 8 * NP);
        __syncthreads();
        As[acol + 0][arow] = av.x;
        As[acol + 1][arow] = av.y;
        *(float4*)&Bs[brow][bcol] = bv;
        __syncthreads();
        #pragma unroll
        for (int kk = 0; kk < 8; kk++) {
            float a[4], bvv[8];
            float4 t0 = *(const float4*)&As[kk][ty * 4];
            a[0]=t0.x; a[1]=t0.y; a[2]=t0.z; a[3]=t0.w;
            float4 u0 = *(const float4*)&Bs[kk][tx * 8];
            float4 u1 = *(const float4*)&Bs[kk][tx * 8 + 4];
            bvv[0]=u0.x; bvv[1]=u0.y; bvv[2]=u0.z; bvv[3]=u0.w;
            bvv[4]=u1.x; bvv[5]=u1.y; bvv[6]=u1.z; bvv[7]=u1.w;
            #pragma unroll
            for (int i = 0; i < 4; i++)
                #pragma unroll
                for (int j = 0; j < 8; j++)
                    acc[i][j] += a[i] * bvv[j];
        }
    }
    #pragma unroll
    for (int i = 0; i < 4; i++) {
        int row = ty * 4 + i;
        float bias = (row < 32) ? bq[row] : bk[row - 32];
        float* dst = ((row < 32) ? (g_q + (b * C8 + row) * NP)
                                 : (g_k + (b * C8 + row - 32) * NP)) + p0 + tx * 8;
        *(float4*)dst       = make_float4(acc[i][0]+bias, acc[i][1]+bias, acc[i][2]+bias, acc[i][3]+bias);
        *(float4*)(dst + 4) = make_float4(acc[i][4]+bias, acc[i][5]+bias, acc[i][6]+bias, acc[i][7]+bias);
    }
}

// ---------------- row softmax over 4096, bf16 in place ----------------
__global__ __launch_bounds__(256) void softmax_kernel() {
    size_t row = blockIdx.x;
    uint32_t* ptr = (uint32_t*)(g_attnh + row * (size_t)NP);
    int tid = threadIdx.x;
    float vals[16];
    float m = -1e30f;
    #pragma unroll
    for (int s = 0; s < 8; s++) {
        uint32_t u = ptr[tid + s * 256];
        float lo = __bfloat162float(__ushort_as_bfloat16((unsigned short)(u & 0xffff)));
        float hi = __bfloat162float(__ushort_as_bfloat16((unsigned short)(u >> 16)));
        vals[2 * s] = lo; vals[2 * s + 1] = hi;
        m = fmaxf(m, fmaxf(lo, hi));
    }
    #pragma unroll
    for (int o = 16; o; o >>= 1) m = fmaxf(m, __shfl_xor_sync(0xffffffffu, m, o));
    __shared__ float shm[8], shs[8];
    int w = tid >> 5, l = tid & 31;
    if (l == 0) shm[w] = m;
    __syncthreads();
    m = fmaxf(fmaxf(fmaxf(shm[0], shm[1]), fmaxf(shm[2], shm[3])),
              fmaxf(fmaxf(shm[4], shm[5]), fmaxf(shm[6], shm[7])));
    float sum = 0.f;
    #pragma unroll
    for (int s = 0; s < 16; s++) {
        vals[s] = __expf(vals[s] - m);
        sum += vals[s];
    }
    #pragma unroll
    for (int o = 16; o; o >>= 1) sum += __shfl_xor_sync(0xffffffffu, sum, o);
    if (l == 0) shs[w] = sum;
    __syncthreads();
    sum = shs[0] + shs[1] + shs[2] + shs[3] + shs[4] + shs[5] + shs[6] + shs[7];
    float inv = 1.0f / sum;
    #pragma unroll
    for (int s = 0; s < 8; s++)
        ptr[tid + s * 256] = pbf2(vals[2 * s] * inv, vals[2 * s + 1] * inv);
}

// ---------------- launcher (R13 structure, 512-thread GEMMs) ----------------
extern "C" void kernel_launch(void* const* d_in, const int* in_sizes, int n_in,
                              void* d_out, int out_size) {
    const float* x     = (const float*)d_in[0];
    const float* w1    = (const float*)d_in[1];
    const float* b1    = (const float*)d_in[2];
    const float* w2    = (const float*)d_in[3];
    const float* b2    = (const float*)d_in[4];
    const float* wq    = (const float*)d_in[5];
    const float* bq    = (const float*)d_in[6];
    const float* wk    = (const float*)d_in[7];
    const float* bk    = (const float*)d_in[8];
    const float* wv    = (const float*)d_in[9];
    const float* bv    = (const float*)d_in[10];
    const float* gamma = (const float*)d_in[11];
    float* out = (float*)d_out;

    cudaFuncSetAttribute(tc_gemm<0, KCONV, 0>, cudaFuncAttributeMaxDynamicSharedMemorySize, SMEM_DYN);
    cudaFuncSetAttribute(tc_gemm<0, KCONV, 1>, cudaFuncAttributeMaxDynamicSharedMemorySize, SMEM_DYN);
    cudaFuncSetAttribute(tc_gemm<1, CC, 0>,    cudaFuncAttributeMaxDynamicSharedMemorySize, SMEM_DYN);
    cudaFuncSetAttribute(tc_gemm<2, C8, 0>,    cudaFuncAttributeMaxDynamicSharedMemorySize, SMEM_DYN);
    cudaFuncSetAttribute(o_gemm_bf16,          cudaFuncAttributeMaxDynamicSharedMemorySize, OSMEM);

    cudaStream_t s1;
    cudaStreamCreateWithFlags(&s1, cudaStreamNonBlocking);
    cudaEvent_t evA, evB, evC, evD;
    cudaEventCreateWithFlags(&evA, cudaEventDisableTiming);
    cudaEventCreateWithFlags(&evB, cudaEventDisableTiming);
    cudaEventCreateWithFlags(&evC, cudaEventDisableTiming);
    cudaEventCreateWithFlags(&evD, cudaEventDisableTiming);

    dim3 g128(NP / 128, CC / 128, BB);   // (32,2,2)

    // fork: wtrans on s1 overlaps pad on main stream
    cudaEventRecord(evA, 0);
    cudaStreamWaitEvent(s1, evA, 0);
    wtrans_kernel<<<dim3(CC, 2), 256, 0, s1>>>(w1, w2);
    pad_kernel<<<BB * CC, 256>>>(x);
    cudaEventRecord(evB, s1);
    cudaStreamWaitEvent(0, evB, 0);

    // conv chain
    tc_gemm<0, KCONV, 0><<<g128, 512, SMEM_DYN>>>(nullptr, b1);
    stats_pad_kernel<<<BB * CC, 256>>>();
    tc_gemm<0, KCONV, 1><<<g128, 512, SMEM_DYN>>>(nullptr, b2);
    stats_norm_kernel<<<BB * CC, 256>>>(x);

    // fork: v-projection (s1) overlaps qk -> energy -> softmax (main)
    cudaEventRecord(evC, 0);
    cudaStreamWaitEvent(s1, evC, 0);
    tc_gemm<1, CC, 0><<<g128, 512, SMEM_DYN, s1>>>(wv, bv);
    qk_gemm<<<dim3(NP / 128, 1, BB), 256>>>(wq, bq, wk, bk);
    tc_gemm<2, C8, 0><<<dim3(NP / 128, NP / 128, BB), 512, SMEM_DYN>>>(nullptr, nullptr);  // energy
    softmax_kernel<<<BB * NP, 256>>>();
    cudaEventRecord(evD, s1);
    cudaStreamWaitEvent(0, evD, 0);

    // join: o-GEMM needs both g_vh (s1) and g_attnh (main)
    o_gemm_bf16<<<g128, 256, OSMEM>>>(gamma, out);
}

// round 16
// speedup vs baseline: 1.2021x; 1.2021x over previous
#include <cuda_runtime.h>
#include <cuda_bf16.h>
#include <math.h>
#include <stdint.h>

#define EPSV 1e-5f
#define BB 2
#define CC 256
#define C8 32
#define NP 4096          // 16*16*16 positions
#define PADN 5832        // 18*18*18
#define KCONV (CC*27)    // 6912

// ---------------- scratch ----------------
__device__ float g_pad[BB*CC*PADN];
__device__ float g_y[BB*CC*NP];
__device__ float g_out[BB*CC*NP];
__device__ float g_q[BB*C8*NP];
__device__ float g_k[BB*C8*NP];
__device__ __nv_bfloat16 g_vh[BB*CC*NP];
__device__ __nv_bfloat16 g_attnh[(size_t)BB*NP*NP];
__device__ float g_wt[CC*KCONV];
__device__ float g_wt2[CC*KCONV];

// padded-offset per conv tap (strides 324/18/1)
__constant__ int c_doff[27] = {
  -343,-342,-341,-325,-324,-323,-307,-306,-305,
   -19, -18, -17,  -1,   0,   1,  17,  18,  19,
   305, 306, 307, 323, 324, 325, 341, 342, 343};

// ---------------- helpers ----------------
__device__ __forceinline__ float tf32r(float x) {
    uint32_t u;
    asm("cvt.rna.tf32.f32 %0, %1;" : "=r"(u) : "f"(x));
    return __uint_as_float(u);
}
__device__ __forceinline__ void mma_tf32(float (&d)[4], const float4 &a, const float2 &b) {
    asm volatile(
        "mma.sync.aligned.m16n8k8.row.col.f32.tf32.tf32.f32 "
        "{%0,%1,%2,%3}, {%4,%5,%6,%7}, {%8,%9}, {%0,%1,%2,%3};\n"
        : "+f"(d[0]), "+f"(d[1]), "+f"(d[2]), "+f"(d[3])
        : "r"(__float_as_uint(a.x)), "r"(__float_as_uint(a.y)),
          "r"(__float_as_uint(a.z)), "r"(__float_as_uint(a.w)),
          "r"(__float_as_uint(b.x)), "r"(__float_as_uint(b.y)));
}
__device__ __forceinline__ void mma_bf16(float (&d)[4], const uint4 &a, const uint2 &b) {
    asm volatile(
        "mma.sync.aligned.m16n8k16.row.col.f32.bf16.bf16.f32 "
        "{%0,%1,%2,%3}, {%4,%5,%6,%7}, {%8,%9}, {%0,%1,%2,%3};\n"
        : "+f"(d[0]), "+f"(d[1]), "+f"(d[2]), "+f"(d[3])
        : "r"(a.x), "r"(a.y), "r"(a.z), "r"(a.w), "r"(b.x), "r"(b.y));
}
__device__ __forceinline__ uint32_t pbf2(float lo, float hi) {
    return (uint32_t)__bfloat16_as_ushort(__float2bfloat16_rn(lo))
         | ((uint32_t)__bfloat16_as_ushort(__float2bfloat16_rn(hi)) << 16);
}

// ---------------- weight transpose (both weights in one launch) ----------------
__global__ __launch_bounds__(256) void wtrans_kernel(const float* __restrict__ w1,
                                                     const float* __restrict__ w2) {
    int co = blockIdx.x;
    int cin = threadIdx.x;
    const float* w   = blockIdx.y ? w2 : w1;
    float*       wt  = blockIdx.y ? g_wt2 : g_wt;
    const float* src = w + (size_t)co * KCONV + (size_t)cin * 27;
    float v[27];
    #pragma unroll
    for (int t = 0; t < 27; t++) v[t] = src[t];
    float* dst = wt + (size_t)co * KCONV + cin;
    #pragma unroll
    for (int t = 0; t < 27; t++) dst[t * 256] = v[t];
}

// ---------------- pad kernel: x -> g_pad (zero-fill then direct interior map) ----------------
__global__ void pad_kernel(const float* __restrict__ x) {
    int bc = blockIdx.x;
    const float* src = x + (size_t)bc * NP;
    float* dst = g_pad + (size_t)bc * PADN;
    int tid = threadIdx.x;
    float4 z4 = make_float4(0.f, 0.f, 0.f, 0.f);
    #pragma unroll
    for (int s = 0; s < 6; s++) {
        int i = tid + s * 256;
        if (i < PADN / 4) *(float4*)(dst + i * 4) = z4;
    }
    __syncthreads();
    #pragma unroll
    for (int s = 0; s < 16; s++) {
        int idx = tid + s * 256;
        int zc = idx & 15, yc = (idx >> 4) & 15, xc = idx >> 8;
        dst[(xc + 1) * 324 + (yc + 1) * 18 + (zc + 1)] = src[idx];
    }
}

// ---------------- block-wide mean/rstd (float4-vectorized reduction) ----------------
__device__ __forceinline__ void block_stats(const float* __restrict__ src,
                                            float& mean, float& rstd) {
    float s = 0.f, ss = 0.f;
    const float4* s4 = (const float4*)src;
    #pragma unroll
    for (int i = threadIdx.x; i < NP / 4; i += 256) {
        float4 v = s4[i];
        s  += v.x + v.y + v.z + v.w;
        ss += v.x * v.x + v.y * v.y + v.z * v.z + v.w * v.w;
    }
    #pragma unroll
    for (int o = 16; o; o >>= 1) {
        s  += __shfl_down_sync(0xffffffffu, s, o);
        ss += __shfl_down_sync(0xffffffffu, ss, o);
    }
    __shared__ float sh_s[8], sh_ss[8], sh_m, sh_r;
    int w = threadIdx.x >> 5, l = threadIdx.x & 31;
    if (l == 0) { sh_s[w] = s; sh_ss[w] = ss; }
    __syncthreads();
    if (threadIdx.x == 0) {
        float S = 0.f, SS = 0.f;
        #pragma unroll
        for (int i = 0; i < 8; i++) { S += sh_s[i]; SS += sh_ss[i]; }
        float m = S * (1.0f / NP);
        float var = SS * (1.0f / NP) - m * m;
        sh_m = m;
        sh_r = rsqrtf(var + EPSV);
    }
    __syncthreads();
    mean = sh_m; rstd = sh_r;
}

// ---------------- fused: stats(g_y[bc]) then instnorm+relu -> g_pad ----------------
__global__ void stats_pad_kernel() {
    int bc = blockIdx.x;
    const float* src = g_y + (size_t)bc * NP;
    float m, r;
    block_stats(src, m, r);
    float* dst = g_pad + (size_t)bc * PADN;
    int tid = threadIdx.x;
    float4 z4 = make_float4(0.f, 0.f, 0.f, 0.f);
    #pragma unroll
    for (int s = 0; s < 6; s++) {
        int i = tid + s * 256;
        if (i < PADN / 4) *(float4*)(dst + i * 4) = z4;
    }
    __syncthreads();
    #pragma unroll
    for (int s = 0; s < 16; s++) {
        int idx = tid + s * 256;
        int zc = idx & 15, yc = (idx >> 4) & 15, xc = idx >> 8;
        dst[(xc + 1) * 324 + (yc + 1) * 18 + (zc + 1)] = fmaxf((src[idx] - m) * r, 0.f);
    }
}

// ---------------- fused: stats(g_y[bc]) then g_out = x + instnorm(g_y), float4 ----------------
__global__ void stats_norm_kernel(const float* __restrict__ x) {
    int bc = blockIdx.x;
    const float* src = g_y + (size_t)bc * NP;
    float m, r;
    block_stats(src, m, r);
    const float4* x4 = (const float4*)(x + (size_t)bc * NP);
    const float4* y4 = (const float4*)src;
    float4* d4 = (float4*)(g_out + (size_t)bc * NP);
    #pragma unroll
    for (int i = threadIdx.x; i < NP / 4; i += 256) {
        float4 a = x4[i], b = y4[i];
        d4[i] = make_float4(a.x + (b.x - m) * r, a.y + (b.y - m) * r,
                            a.z + (b.z - m) * r, a.w + (b.w - m) * r);
    }
}

// ============================================================================
// Pipelined mma.sync tf32 GEMM, 128x128 tile, k-step 32, 2-stage smem,
// 256 threads (proven optimal config: R13).
// MODE 0 (CONV):   A=wt[co][(tap,cin)],  B=im2col(g_pad), dst=g_y fp32 (+bias)
// MODE 1 (VPROJ):  A=Aext(wv),           B=g_out[c][p],   dst=g_vh bf16 (+bias)
// MODE 2 (ENERGY): A=q^T strided, B=k strided, KTOT=32,   dst=g_attnh bf16
// ============================================================================
#define STG_FLOATS 8320
#define SMEM_DYN (2 * STG_FLOATS * 4)

template<int MODE, int KTOT, int CONVSEL>
__global__ __launch_bounds__(256, 1)
void tc_gemm(const float* __restrict__ Aext, const float* __restrict__ bias) {
    constexpr int NCH = KTOT / 32;
    extern __shared__ float sm[];
    const int tid = threadIdx.x, wid = tid >> 5, lane = tid & 31;
    const int bb = blockIdx.z;
    const int m0 = blockIdx.y * 128, n0 = blockIdx.x * 128;

    // ---- A loader ----
    const int amt = tid >> 5;
    const int arg = (tid >> 2) & 7;
    const int akb = tid & 3;
    const float* aptr0 = nullptr;
    const float* aptr1 = nullptr;
    const float* aqbase = nullptr;
    {
        int m = m0 + amt * 16 + arg;
        if (MODE == 2) {
            aqbase = g_q + (size_t)bb * C8 * NP + m;
        } else {
            const float* base = (MODE == 0) ? (CONVSEL ? g_wt2 : g_wt) : Aext;
            aptr0 = base + (size_t)m * KTOT + akb * 8;
            aptr1 = base + (size_t)(m + 8) * KTOT + akb * 8;
        }
    }

    // ---- B loader ----
    const int bn = tid >> 1;
    const int bkh = (tid & 1) * 2;
    int pofs = 0;
    const float* bbase = nullptr;
    if (MODE == 0) {
        int p = n0 + bn;
        int pz = p & 15, py = (p >> 4) & 15, px = p >> 8;
        pofs = (px + 1) * 324 + (py + 1) * 18 + (pz + 1);
        bbase = g_pad + (size_t)bb * CC * PADN;
    } else if (MODE == 1) {
        bbase = g_out + (size_t)bb * CC * NP + n0 + bn;
    } else {
        bbase = g_k + (size_t)bb * C8 * NP + n0 + bn;
    }

    float ar0[8], ar1[8], br[16];

    #define LOAD_A(ch_) do { \
        if (MODE == 2) { \
            _Pragma("unroll") \
            for (int c = 0; c < 8; c++) { \
                size_t o_ = (size_t)((ch_) * 32 + akb * 8 + c) * NP; \
                ar0[c] = aqbase[o_]; \
                ar1[c] = aqbase[o_ + 8]; \
            } \
        } else { \
            *(float4*)(ar0)     = *(const float4*)(aptr0 + (size_t)(ch_) * 32); \
            *(float4*)(ar0 + 4) = *(const float4*)(aptr0 + (size_t)(ch_) * 32 + 4); \
            *(float4*)(ar1)     = *(const float4*)(aptr1 + (size_t)(ch_) * 32); \
            *(float4*)(ar1 + 4) = *(const float4*)(aptr1 + (size_t)(ch_) * 32 + 4); \
        } \
    } while (0)

    #define LOAD_B(ch_) do { \
        if (MODE == 0) { \
            _Pragma("unroll") \
            for (int t = 0; t < 2; t++) { \
                _Pragma("unroll") \
                for (int c = 0; c < 8; c++) { \
                    int k = (ch_) * 32 + (bkh + t) * 8 + c; \
                    int tap = k >> 8, cin = k & 255; \
                    br[t * 8 + c] = bbase[(size_t)cin * PADN + c_doff[tap] + pofs]; \
                } \
            } \
        } else { \
            _Pragma("unroll") \
            for (int t = 0; t < 2; t++) { \
                _Pragma("unroll") \
                for (int c = 0; c < 8; c++) { \
                    int k = (ch_) * 32 + (bkh + t) * 8 + c; \
                    br[t * 8 + c] = bbase[(size_t)k * NP]; \
                } \
            } \
        } \
    } while (0)

    #define STORE_AB(stg_) do { \
        float* As_ = sm + (stg_) * STG_FLOATS + amt * 512 + akb * 128 + arg * 16; \
        _Pragma("unroll") \
        for (int c = 0; c < 4; c++) { \
            *(float4*)(As_ + c * 4) = make_float4( \
                tf32r(ar0[c]), tf32r(ar1[c]), tf32r(ar0[c + 4]), tf32r(ar1[c + 4])); \
        } \
        float* Bs_ = sm + (stg_) * STG_FLOATS + 4096 + (bn >> 3) * 264 + (bn & 7) * 8; \
        _Pragma("unroll") \
        for (int t = 0; t < 2; t++) { \
            int kbb = bkh + t; \
            _Pragma("unroll") \
            for (int c = 0; c < 4; c++) { \
                *(float2*)(Bs_ + kbb * 64 + c * 2) = \
                    make_float2(tf32r(br[t * 8 + c]), tf32r(br[t * 8 + c + 4])); \
            } \
        } \
    } while (0)

    const int wm = wid & 1, wn = wid >> 1;
    float acc[4][4][4];
    #pragma unroll
    for (int i = 0; i < 4; i++)
        #pragma unroll
        for (int j = 0; j < 4; j++)
            #pragma unroll
            for (int k = 0; k < 4; k++) acc[i][j][k] = 0.f;

    LOAD_A(0); LOAD_B(0);
    STORE_AB(0);
    if (NCH > 1) { LOAD_A(1); LOAD_B(1); }
    __syncthreads();

    for (int ch = 0; ch < NCH; ch++) {
        int cur = ch & 1;
        if (ch + 1 < NCH) STORE_AB(cur ^ 1);
        if (ch + 2 < NCH) { LOAD_A(ch + 2); LOAD_B(ch + 2); }

        const float* As_ = sm + cur * STG_FLOATS;
        const float* Bs_ = As_ + 4096;
        #pragma unroll
        for (int kb = 0; kb < 4; kb++) {
            float4 af[4]; float2 bf[4];
            #pragma unroll
            for (int mt = 0; mt < 4; mt++)
                af[mt] = *(const float4*)(As_ + (wm * 4 + mt) * 512 + kb * 128 + lane * 4);
            #pragma unroll
            for (int nt = 0; nt < 4; nt++)
                bf[nt] = *(const float2*)(Bs_ + (wn * 4 + nt) * 264 + kb * 64 + lane * 2);
            #pragma unroll
            for (int mt = 0; mt < 4; mt++)
                #pragma unroll
                for (int nt = 0; nt < 4; nt++)
                    mma_tf32(acc[mt][nt], af[mt], bf[nt]);
        }
        __syncthreads();
    }

    #undef LOAD_A
    #undef LOAD_B
    #undef STORE_AB

    const int g = lane >> 2, tg = lane & 3;
    #pragma unroll
    for (int mt = 0; mt < 4; mt++) {
        int m = m0 + wm * 64 + mt * 16 + g;
        float bs0 = 0.f, bs1 = 0.f;
        if (MODE != 2) { bs0 = bias[m]; bs1 = bias[m + 8]; }
        #pragma unroll
        for (int nt = 0; nt < 4; nt++) {
            int n = n0 + wn * 32 + nt * 8 + tg * 2;
            if (MODE == 0) {
                size_t base0 = (size_t)(bb * CC + m) * NP + n;
                size_t base1 = base0 + (size_t)8 * NP;
                *(float2*)(g_y + base0) = make_float2(acc[mt][nt][0] + bs0, acc[mt][nt][1] + bs0);
                *(float2*)(g_y + base1) = make_float2(acc[mt][nt][2] + bs1, acc[mt][nt][3] + bs1);
            } else if (MODE == 1) {
                size_t base0 = (size_t)(bb * CC + m) * NP + n;
                size_t base1 = base0 + (size_t)8 * NP;
                *(uint32_t*)(g_vh + base0) = pbf2(acc[mt][nt][0] + bs0, acc[mt][nt][1] + bs0);
                *(uint32_t*)(g_vh + base1) = pbf2(acc[mt][nt][2] + bs1, acc[mt][nt][3] + bs1);
            } else {
                size_t base0 = ((size_t)bb * NP + m) * NP + n;
                size_t base1 = base0 + (size_t)8 * NP;
                *(uint32_t*)(g_attnh + base0) = pbf2(acc[mt][nt][0], acc[mt][nt][1]);
                *(uint32_t*)(g_attnh + base1) = pbf2(acc[mt][nt][2], acc[mt][nt][3]);
            }
        }
    }
}

// ============================================================================
// o-GEMM, bf16 m16n8k16: o[c,i] = sum_j v[c,j]*attnh[i,j]; dout = gamma*o+g_out
// ============================================================================
#define OA_U32 2048
#define OB_U32 (16*136)
#define OSTG_U32 (OA_U32 + OB_U32)
#define OSMEM (2 * OSTG_U32 * 4)

__global__ __launch_bounds__(256, 1)
void o_gemm_bf16(const float* __restrict__ gamma, float* __restrict__ dout) {
    extern __shared__ uint32_t smu[];
    const int tid = threadIdx.x, wid = tid >> 5, lane = tid & 31;
    const int bb = blockIdx.z, m0 = blockIdx.y * 128, i0 = blockIdx.x * 128;
    const int wm = wid & 1, wn = wid >> 1;

    const uint32_t *av0 = nullptr, *av1 = nullptr;
    uint32_t aoff = 0;
    if (tid < 128) {
        int rpi = tid >> 1, akb = tid & 1;
        int mt = rpi >> 3, rp = rpi & 7;
        int m = m0 + mt * 16 + rp;
        av0 = (const uint32_t*)(g_vh + (size_t)(bb * CC + m) * NP) + akb * 8;
        av1 = av0 + (size_t)4 * NP;
        aoff = mt * 256 + akb * 128 + rp * 16;
    }
    const int bn = tid >> 1, bkb = tid & 1;
    const __nv_bfloat16* bptr = g_attnh + ((size_t)bb * NP + i0 + bn) * NP + bkb * 16;
    const uint32_t boff = OA_U32 + (bn >> 3) * 136 + bkb * 68 + (bn & 7) * 8;

    uint32_t a0u[8], a1u[8];
    uint32_t brg[8];

    #define OLOAD(ch_) do { \
        if (tid < 128) { \
            *(uint4*)(a0u)     = *(const uint4*)(av0 + (size_t)(ch_) * 16); \
            *(uint4*)(a0u + 4) = *(const uint4*)(av0 + (size_t)(ch_) * 16 + 4); \
            *(uint4*)(a1u)     = *(const uint4*)(av1 + (size_t)(ch_) * 16); \
            *(uint4*)(a1u + 4) = *(const uint4*)(av1 + (size_t)(ch_) * 16 + 4); \
        } \
        *(uint4*)(brg)     = *(const uint4*)(bptr + (size_t)(ch_) * 32); \
        *(uint4*)(brg + 4) = *(const uint4*)(bptr + (size_t)(ch_) * 32 + 8); \
    } while (0)

    #define OSTORE(stg_) do { \
        uint32_t* s_ = smu + (stg_) * OSTG_U32; \
        if (tid < 128) { \
            _Pragma("unroll") \
            for (int t = 0; t < 4; t++) { \
                *(uint4*)(s_ + aoff + t * 4) = \
                    make_uint4(a0u[t], a1u[t], a0u[t + 4], a1u[t + 4]); \
            } \
        } \
        _Pragma("unroll") \
        for (int t = 0; t < 4; t++) \
            *(uint2*)(s_ + boff + t * 2) = make_uint2(brg[t], brg[t + 4]); \
    } while (0)

    float acc[4][4][4];
    #pragma unroll
    for (int i = 0; i < 4; i++)
        #pragma unroll
        for (int j = 0; j < 4; j++)
            #pragma unroll
            for (int k = 0; k < 4; k++) acc[i][j][k] = 0.f;

    OLOAD(0); OSTORE(0); OLOAD(1);
    __syncthreads();

    constexpr int NCH = NP / 32;   // 128
    for (int ch = 0; ch < NCH; ch++) {
        int cur = ch & 1;
        if (ch + 1 < NCH) OSTORE(cur ^ 1);
        if (ch + 2 < NCH) OLOAD(ch + 2);

        const uint32_t* s_ = smu + cur * OSTG_U32;
        #pragma unroll
        for (int kb = 0; kb < 2; kb++) {
            uint4 af[4]; uint2 bf[4];
            #pragma unroll
            for (int mt = 0; mt < 4; mt++)
                af[mt] = *(const uint4*)(s_ + (wm * 4 + mt) * 256 + kb * 128 + lane * 4);
            #pragma unroll
            for (int nt = 0; nt < 4; nt++)
                bf[nt] = *(const uint2*)(s_ + OA_U32 + (wn * 4 + nt) * 136 + kb * 68 + lane * 2);
            #pragma unroll
            for (int mt = 0; mt < 4; mt++)
                #pragma unroll
                for (int nt = 0; nt < 4; nt++)
                    mma_bf16(acc[mt][nt], af[mt], bf[nt]);
        }
        __syncthreads();
    }

    #undef OLOAD
    #undef OSTORE

    const int g = lane >> 2, tg = lane & 3;
    const float gm = gamma[0];
    #pragma unroll
    for (int mt = 0; mt < 4; mt++) {
        int m = m0 + wm * 64 + mt * 16 + g;
        #pragma unroll
        for (int nt = 0; nt < 4; nt++) {
            int n = i0 + wn * 32 + nt * 8 + tg * 2;
            size_t base0 = (size_t)(bb * CC + m) * NP + n;
            size_t base1 = base0 + (size_t)8 * NP;
            const float* r0 = g_out + base0;
            const float* r1 = g_out + base1;
            *(float2*)(dout + base0) =
                make_float2(gm * acc[mt][nt][0] + r0[0], gm * acc[mt][nt][1] + r0[1]);
            *(float2*)(dout + base1) =
                make_float2(gm * acc[mt][nt][2] + r1[0], gm * acc[mt][nt][3] + r1[1]);
        }
    }
}

// ---------------- q and k projections fused (FFMA, small) ----------------
__global__ __launch_bounds__(256) void qk_gemm(const float* __restrict__ wq, const float* __restrict__ bq,
                                               const float* __restrict__ wk, const float* __restrict__ bk) {
    __shared__ float As[8][64];
    __shared__ float Bs[8][128];
    int tid = threadIdx.x, b = blockIdx.z;
    int p0 = blockIdx.x * 128;
    int arow = tid >> 2;
    int acol = (tid & 3) * 2;
    const float* ap = ((arow < 32) ? (wq + arow * CC) : (wk + (arow - 32) * CC)) + acol;
    int brow = tid >> 5, bcol = (tid & 31) * 4;
    const float* bp = g_out + (b * CC + brow) * NP + p0 + bcol;
    int ty = tid >> 4, tx = tid & 15;
    float acc[4][8];
    #pragma unroll
    for (int i = 0; i < 4; i++)
        #pragma unroll
        for (int j = 0; j < 8; j++) acc[i][j] = 0.f;

    for (int it = 0; it < CC / 8; ++it) {
        float2 av = *(const float2*)(ap + it * 8);
        float4 bv = *(const float4*)(bp + (size_t)it * 8 * NP);
        __syncthreads();
        As[acol + 0][arow] = av.x;
        As[acol + 1][arow] = av.y;
        *(float4*)&Bs[brow][bcol] = bv;
        __syncthreads();
        #pragma unroll
        for (int kk = 0; kk < 8; kk++) {
            float a[4], bvv[8];
            float4 t0 = *(const float4*)&As[kk][ty * 4];
            a[0]=t0.x; a[1]=t0.y; a[2]=t0.z; a[3]=t0.w;
            float4 u0 = *(const float4*)&Bs[kk][tx * 8];
            float4 u1 = *(const float4*)&Bs[kk][tx * 8 + 4];
            bvv[0]=u0.x; bvv[1]=u0.y; bvv[2]=u0.z; bvv[3]=u0.w;
            bvv[4]=u1.x; bvv[5]=u1.y; bvv[6]=u1.z; bvv[7]=u1.w;
            #pragma unroll
            for (int i = 0; i < 4; i++)
                #pragma unroll
                for (int j = 0; j < 8; j++)
                    acc[i][j] += a[i] * bvv[j];
        }
    }
    #pragma unroll
    for (int i = 0; i < 4; i++) {
        int row = ty * 4 + i;
        float bias = (row < 32) ? bq[row] : bk[row - 32];
        float* dst = ((row < 32) ? (g_q + (b * C8 + row) * NP)
                                 : (g_k + (b * C8 + row - 32) * NP)) + p0 + tx * 8;
        *(float4*)dst       = make_float4(acc[i][0]+bias, acc[i][1]+bias, acc[i][2]+bias, acc[i][3]+bias);
        *(float4*)(dst + 4) = make_float4(acc[i][4]+bias, acc[i][5]+bias, acc[i][6]+bias, acc[i][7]+bias);
    }
}

// ---------------- row softmax over 4096, bf16 in place (u32-vectorized) ----------------
__global__ __launch_bounds__(256) void softmax_kernel() {
    size_t row = blockIdx.x;
    uint32_t* ptr = (uint32_t*)(g_attnh + row * (size_t)NP);
    int tid = threadIdx.x;
    float vals[16];
    float m = -1e30f;
    #pragma unroll
    for (int s = 0; s < 8; s++) {
        uint32_t u = ptr[tid + s * 256];
        float lo = __bfloat162float(__ushort_as_bfloat16((unsigned short)(u & 0xffff)));
        float hi = __bfloat162float(__ushort_as_bfloat16((unsigned short)(u >> 16)));
        vals[2 * s] = lo; vals[2 * s + 1] = hi;
        m = fmaxf(m, fmaxf(lo, hi));
    }
    #pragma unroll
    for (int o = 16; o; o >>= 1) m = fmaxf(m, __shfl_xor_sync(0xffffffffu, m, o));
    __shared__ float shm[8], shs[8];
    int w = tid >> 5, l = tid & 31;
    if (l == 0) shm[w] = m;
    __syncthreads();
    m = fmaxf(fmaxf(fmaxf(shm[0], shm[1]), fmaxf(shm[2], shm[3])),
              fmaxf(fmaxf(shm[4], shm[5]), fmaxf(shm[6], shm[7])));
    float sum = 0.f;
    #pragma unroll
    for (int s = 0; s < 16; s++) {
        vals[s] = __expf(vals[s] - m);
        sum += vals[s];
    }
    #pragma unroll
    for (int o = 16; o; o >>= 1) sum += __shfl_xor_sync(0xffffffffu, sum, o);
    if (l == 0) shs[w] = sum;
    __syncthreads();
    sum = shs[0] + shs[1] + shs[2] + shs[3] + shs[4] + shs[5] + shs[6] + shs[7];
    float inv = 1.0f / sum;
    #pragma unroll
    for (int s = 0; s < 8; s++)
        ptr[tid + s * 256] = pbf2(vals[2 * s] * inv, vals[2 * s + 1] * inv);
}

// ---------------- launcher: forked-stream capture graph (R13) ----------------
extern "C" void kernel_launch(void* const* d_in, const int* in_sizes, int n_in,
                              void* d_out, int out_size) {
    const float* x     = (const float*)d_in[0];
    const float* w1    = (const float*)d_in[1];
    const float* b1    = (const float*)d_in[2];
    const float* w2    = (const float*)d_in[3];
    const float* b2    = (const float*)d_in[4];
    const float* wq    = (const float*)d_in[5];
    const float* bq    = (const float*)d_in[6];
    const float* wk    = (const float*)d_in[7];
    const float* bk    = (const float*)d_in[8];
    const float* wv    = (const float*)d_in[9];
    const float* bv    = (const float*)d_in[10];
    const float* gamma = (const float*)d_in[11];
    float* out = (float*)d_out;

    cudaFuncSetAttribute(tc_gemm<0, KCONV, 0>, cudaFuncAttributeMaxDynamicSharedMemorySize, SMEM_DYN);
    cudaFuncSetAttribute(tc_gemm<0, KCONV, 1>, cudaFuncAttributeMaxDynamicSharedMemorySize, SMEM_DYN);
    cudaFuncSetAttribute(tc_gemm<1, CC, 0>,    cudaFuncAttributeMaxDynamicSharedMemorySize, SMEM_DYN);
    cudaFuncSetAttribute(tc_gemm<2, C8, 0>,    cudaFuncAttributeMaxDynamicSharedMemorySize, SMEM_DYN);
    cudaFuncSetAttribute(o_gemm_bf16,          cudaFuncAttributeMaxDynamicSharedMemorySize, OSMEM);

    // Side stream (created per call, never destroyed: destroying a stream in an
    // active capture invalidates the capture).
    cudaStream_t s1;
    cudaStreamCreateWithFlags(&s1, cudaStreamNonBlocking);
    cudaEvent_t evA, evB, evC, evD;
    cudaEventCreateWithFlags(&evA, cudaEventDisableTiming);
    cudaEventCreateWithFlags(&evB, cudaEventDisableTiming);
    cudaEventCreateWithFlags(&evC, cudaEventDisableTiming);
    cudaEventCreateWithFlags(&evD, cudaEventDisableTiming);

    dim3 g128(NP / 128, CC / 128, BB);   // (32,2,2)

    // fork: wtrans on s1 overlaps pad on main stream
    cudaEventRecord(evA, 0);
    cudaStreamWaitEvent(s1, evA, 0);
    wtrans_kernel<<<dim3(CC, 2), 256, 0, s1>>>(w1, w2);
    pad_kernel<<<BB * CC, 256>>>(x);
    cudaEventRecord(evB, s1);
    cudaStreamWaitEvent(0, evB, 0);

    // conv chain (serial by data dependence)
    tc_gemm<0, KCONV, 0><<<g128, 256, SMEM_DYN>>>(nullptr, b1);
    stats_pad_kernel<<<BB * CC, 256>>>();
    tc_gemm<0, KCONV, 1><<<g128, 256, SMEM_DYN>>>(nullptr, b2);
    stats_norm_kernel<<<BB * CC, 256>>>(x);

    // fork: v-projection (s1) overlaps qk -> energy -> softmax (main)
    cudaEventRecord(evC, 0);
    cudaStreamWaitEvent(s1, evC, 0);
    tc_gemm<1, CC, 0><<<g128, 256, SMEM_DYN, s1>>>(wv, bv);
    qk_gemm<<<dim3(NP / 128, 1, BB), 256>>>(wq, bq, wk, bk);
    tc_gemm<2, C8, 0><<<dim3(NP / 128, NP / 128, BB), 256, SMEM_DYN>>>(nullptr, nullptr);  // energy
    softmax_kernel<<<BB * NP, 256>>>();
    cudaEventRecord(evD, s1);
    cudaStreamWaitEvent(0, evD, 0);

    // join: o-GEMM needs both g_vh (s1) and g_attnh (main)
    o_gemm_bf16<<<g128, 256, OSMEM>>>(gamma, out);
}

// round 17
// speedup vs baseline: 1.3171x; 1.0957x over previous
#include <cuda_runtime.h>
#include <cuda_bf16.h>
#include <math.h>
#include <stdint.h>

#define EPSV 1e-5f
#define BB 2
#define CC 256
#define C8 32
#define NP 4096          // 16*16*16 positions
#define PADN 5832        // 18*18*18
#define KCONV (CC*27)    // 6912

// ---------------- scratch ----------------
__device__ float g_pad[BB*CC*PADN];   // PRE-ROUNDED tf32 (consumed only by conv GEMM)
__device__ float g_y[BB*CC*NP];
__device__ float g_out[BB*CC*NP];
__device__ float g_q[BB*C8*NP];       // PRE-ROUNDED tf32 (consumed only by energy GEMM)
__device__ float g_k[BB*C8*NP];       // PRE-ROUNDED tf32
__device__ __nv_bfloat16 g_vh[BB*CC*NP];
__device__ __nv_bfloat16 g_attnh[(size_t)BB*NP*NP];
__device__ float g_wt[CC*KCONV];      // PRE-ROUNDED tf32 transposed conv1 weights
__device__ float g_wt2[CC*KCONV];     // PRE-ROUNDED tf32 transposed conv2 weights

// padded-offset per conv tap (strides 324/18/1)
__constant__ int c_doff[27] = {
  -343,-342,-341,-325,-324,-323,-307,-306,-305,
   -19, -18, -17,  -1,   0,   1,  17,  18,  19,
   305, 306, 307, 323, 324, 325, 341, 342, 343};

// ---------------- helpers ----------------
__device__ __forceinline__ float tf32r(float x) {
    uint32_t u;
    asm("cvt.rna.tf32.f32 %0, %1;" : "=r"(u) : "f"(x));
    return __uint_as_float(u);
}
__device__ __forceinline__ void mma_tf32(float (&d)[4], const float4 &a, const float2 &b) {
    asm volatile(
        "mma.sync.aligned.m16n8k8.row.col.f32.tf32.tf32.f32 "
        "{%0,%1,%2,%3}, {%4,%5,%6,%7}, {%8,%9}, {%0,%1,%2,%3};\n"
        : "+f"(d[0]), "+f"(d[1]), "+f"(d[2]), "+f"(d[3])
        : "r"(__float_as_uint(a.x)), "r"(__float_as_uint(a.y)),
          "r"(__float_as_uint(a.z)), "r"(__float_as_uint(a.w)),
          "r"(__float_as_uint(b.x)), "r"(__float_as_uint(b.y)));
}
__device__ __forceinline__ void mma_bf16(float (&d)[4], const uint4 &a, const uint2 &b) {
    asm volatile(
        "mma.sync.aligned.m16n8k16.row.col.f32.bf16.bf16.f32 "
        "{%0,%1,%2,%3}, {%4,%5,%6,%7}, {%8,%9}, {%0,%1,%2,%3};\n"
        : "+f"(d[0]), "+f"(d[1]), "+f"(d[2]), "+f"(d[3])
        : "r"(a.x), "r"(a.y), "r"(a.z), "r"(a.w), "r"(b.x), "r"(b.y));
}
__device__ __forceinline__ uint32_t pbf2(float lo, float hi) {
    return (uint32_t)__bfloat16_as_ushort(__float2bfloat16_rn(lo))
         | ((uint32_t)__bfloat16_as_ushort(__float2bfloat16_rn(hi)) << 16);
}

// ---------------- weight transpose (both weights, tf32 pre-round) ----------------
__global__ __launch_bounds__(256) void wtrans_kernel(const float* __restrict__ w1,
                                                     const float* __restrict__ w2) {
    int co = blockIdx.x;
    int cin = threadIdx.x;
    const float* w   = blockIdx.y ? w2 : w1;
    float*       wt  = blockIdx.y ? g_wt2 : g_wt;
    const float* src = w + (size_t)co * KCONV + (size_t)cin * 27;
    float v[27];
    #pragma unroll
    for (int t = 0; t < 27; t++) v[t] = src[t];
    float* dst = wt + (size_t)co * KCONV + cin;
    #pragma unroll
    for (int t = 0; t < 27; t++) dst[t * 256] = tf32r(v[t]);
}

// ---------------- pad kernel: x -> g_pad (tf32 pre-round) ----------------
__global__ void pad_kernel(const float* __restrict__ x) {
    int bc = blockIdx.x;
    const float* src = x + (size_t)bc * NP;
    float* dst = g_pad + (size_t)bc * PADN;
    int tid = threadIdx.x;
    float4 z4 = make_float4(0.f, 0.f, 0.f, 0.f);
    #pragma unroll
    for (int s = 0; s < 6; s++) {
        int i = tid + s * 256;
        if (i < PADN / 4) *(float4*)(dst + i * 4) = z4;
    }
    __syncthreads();
    #pragma unroll
    for (int s = 0; s < 16; s++) {
        int idx = tid + s * 256;
        int zc = idx & 15, yc = (idx >> 4) & 15, xc = idx >> 8;
        dst[(xc + 1) * 324 + (yc + 1) * 18 + (zc + 1)] = tf32r(src[idx]);
    }
}

// ---------------- block-wide mean/rstd (float4-vectorized reduction) ----------------
__device__ __forceinline__ void block_stats(const float* __restrict__ src,
                                            float& mean, float& rstd) {
    float s = 0.f, ss = 0.f;
    const float4* s4 = (const float4*)src;
    #pragma unroll
    for (int i = threadIdx.x; i < NP / 4; i += 256) {
        float4 v = s4[i];
        s  += v.x + v.y + v.z + v.w;
        ss += v.x * v.x + v.y * v.y + v.z * v.z + v.w * v.w;
    }
    #pragma unroll
    for (int o = 16; o; o >>= 1) {
        s  += __shfl_down_sync(0xffffffffu, s, o);
        ss += __shfl_down_sync(0xffffffffu, ss, o);
    }
    __shared__ float sh_s[8], sh_ss[8], sh_m, sh_r;
    int w = threadIdx.x >> 5, l = threadIdx.x & 31;
    if (l == 0) { sh_s[w] = s; sh_ss[w] = ss; }
    __syncthreads();
    if (threadIdx.x == 0) {
        float S = 0.f, SS = 0.f;
        #pragma unroll
        for (int i = 0; i < 8; i++) { S += sh_s[i]; SS += sh_ss[i]; }
        float m = S * (1.0f / NP);
        float var = SS * (1.0f / NP) - m * m;
        sh_m = m;
        sh_r = rsqrtf(var + EPSV);
    }
    __syncthreads();
    mean = sh_m; rstd = sh_r;
}

// ---------------- fused: stats(g_y[bc]) then instnorm+relu -> g_pad (tf32) ----------------
__global__ void stats_pad_kernel() {
    int bc = blockIdx.x;
    const float* src = g_y + (size_t)bc * NP;
    float m, r;
    block_stats(src, m, r);
    float* dst = g_pad + (size_t)bc * PADN;
    int tid = threadIdx.x;
    float4 z4 = make_float4(0.f, 0.f, 0.f, 0.f);
    #pragma unroll
    for (int s = 0; s < 6; s++) {
        int i = tid + s * 256;
        if (i < PADN / 4) *(float4*)(dst + i * 4) = z4;
    }
    __syncthreads();
    #pragma unroll
    for (int s = 0; s < 16; s++) {
        int idx = tid + s * 256;
        int zc = idx & 15, yc = (idx >> 4) & 15, xc = idx >> 8;
        dst[(xc + 1) * 324 + (yc + 1) * 18 + (zc + 1)] =
            tf32r(fmaxf((src[idx] - m) * r, 0.f));
    }
}

// ---------------- fused: stats(g_y[bc]) then g_out = x + instnorm(g_y), float4 ----------------
__global__ void stats_norm_kernel(const float* __restrict__ x) {
    int bc = blockIdx.x;
    const float* src = g_y + (size_t)bc * NP;
    float m, r;
    block_stats(src, m, r);
    const float4* x4 = (const float4*)(x + (size_t)bc * NP);
    const float4* y4 = (const float4*)src;
    float4* d4 = (float4*)(g_out + (size_t)bc * NP);
    #pragma unroll
    for (int i = threadIdx.x; i < NP / 4; i += 256) {
        float4 a = x4[i], b = y4[i];
        d4[i] = make_float4(a.x + (b.x - m) * r, a.y + (b.y - m) * r,
                            a.z + (b.z - m) * r, a.w + (b.w - m) * r);
    }
}

// ============================================================================
// Pipelined mma.sync tf32 GEMM, 128x128 tile, k-step 32, 2-stage smem,
// 256 threads (proven optimal config).
// MODE 0 (CONV):   A=wt (pre-tf32), B=im2col(g_pad, pre-tf32) -> NO mainloop cvt
// MODE 1 (VPROJ):  A=Aext(wv) fp32, B=g_out fp32             -> cvt in STORE
// MODE 2 (ENERGY): A=g_q (pre-tf32), B=g_k (pre-tf32)        -> NO mainloop cvt
// ============================================================================
#define STG_FLOATS 8320
#define SMEM_DYN (2 * STG_FLOATS * 4)

template<int MODE, int KTOT, int CONVSEL>
__global__ __launch_bounds__(256, 1)
void tc_gemm(const float* __restrict__ Aext, const float* __restrict__ bias) {
    constexpr int NCH = KTOT / 32;
    extern __shared__ float sm[];
    const int tid = threadIdx.x, wid = tid >> 5, lane = tid & 31;
    const int bb = blockIdx.z;
    const int m0 = blockIdx.y * 128, n0 = blockIdx.x * 128;

    // ---- A loader ----
    const int amt = tid >> 5;
    const int arg = (tid >> 2) & 7;
    const int akb = tid & 3;
    const float* aptr0 = nullptr;
    const float* aptr1 = nullptr;
    const float* aqbase = nullptr;
    {
        int m = m0 + amt * 16 + arg;
        if (MODE == 2) {
            aqbase = g_q + (size_t)bb * C8 * NP + m;
        } else {
            const float* base = (MODE == 0) ? (CONVSEL ? g_wt2 : g_wt) : Aext;
            aptr0 = base + (size_t)m * KTOT + akb * 8;
            aptr1 = base + (size_t)(m + 8) * KTOT + akb * 8;
        }
    }

    // ---- B loader ----
    const int bn = tid >> 1;
    const int bkh = (tid & 1) * 2;
    int pofs = 0;
    const float* bbase = nullptr;
    if (MODE == 0) {
        int p = n0 + bn;
        int pz = p & 15, py = (p >> 4) & 15, px = p >> 8;
        pofs = (px + 1) * 324 + (py + 1) * 18 + (pz + 1);
        bbase = g_pad + (size_t)bb * CC * PADN;
    } else if (MODE == 1) {
        bbase = g_out + (size_t)bb * CC * NP + n0 + bn;
    } else {
        bbase = g_k + (size_t)bb * C8 * NP + n0 + bn;
    }

    float ar0[8], ar1[8], br[16];

    // cvt only needed for MODE 1 (fp32 sources); MODE 0/2 sources pre-rounded.
    #define CVF(x_) ((MODE == 1) ? tf32r(x_) : (x_))

    #define LOAD_A(ch_) do { \
        if (MODE == 2) { \
            _Pragma("unroll") \
            for (int c = 0; c < 8; c++) { \
                size_t o_ = (size_t)((ch_) * 32 + akb * 8 + c) * NP; \
                ar0[c] = aqbase[o_]; \
                ar1[c] = aqbase[o_ + 8]; \
            } \
        } else { \
            *(float4*)(ar0)     = *(const float4*)(aptr0 + (size_t)(ch_) * 32); \
            *(float4*)(ar0 + 4) = *(const float4*)(aptr0 + (size_t)(ch_) * 32 + 4); \
            *(float4*)(ar1)     = *(const float4*)(aptr1 + (size_t)(ch_) * 32); \
            *(float4*)(ar1 + 4) = *(const float4*)(aptr1 + (size_t)(ch_) * 32 + 4); \
        } \
    } while (0)

    #define LOAD_B(ch_) do { \
        if (MODE == 0) { \
            _Pragma("unroll") \
            for (int t = 0; t < 2; t++) { \
                _Pragma("unroll") \
                for (int c = 0; c < 8; c++) { \
                    int k = (ch_) * 32 + (bkh + t) * 8 + c; \
                    int tap = k >> 8, cin = k & 255; \
                    br[t * 8 + c] = bbase[(size_t)cin * PADN + c_doff[tap] + pofs]; \
                } \
            } \
        } else { \
            _Pragma("unroll") \
            for (int t = 0; t < 2; t++) { \
                _Pragma("unroll") \
                for (int c = 0; c < 8; c++) { \
                    int k = (ch_) * 32 + (bkh + t) * 8 + c; \
                    br[t * 8 + c] = bbase[(size_t)k * NP]; \
                } \
            } \
        } \
    } while (0)

    #define STORE_AB(stg_) do { \
        float* As_ = sm + (stg_) * STG_FLOATS + amt * 512 + akb * 128 + arg * 16; \
        _Pragma("unroll") \
        for (int c = 0; c < 4; c++) { \
            *(float4*)(As_ + c * 4) = make_float4( \
                CVF(ar0[c]), CVF(ar1[c]), CVF(ar0[c + 4]), CVF(ar1[c + 4])); \
        } \
        float* Bs_ = sm + (stg_) * STG_FLOATS + 4096 + (bn >> 3) * 264 + (bn & 7) * 8; \
        _Pragma("unroll") \
        for (int t = 0; t < 2; t++) { \
            int kbb = bkh + t; \
            _Pragma("unroll") \
            for (int c = 0; c < 4; c++) { \
                *(float2*)(Bs_ + kbb * 64 + c * 2) = \
                    make_float2(CVF(br[t * 8 + c]), CVF(br[t * 8 + c + 4])); \
            } \
        } \
    } while (0)

    const int wm = wid & 1, wn = wid >> 1;
    float acc[4][4][4];
    #pragma unroll
    for (int i = 0; i < 4; i++)
        #pragma unroll
        for (int j = 0; j < 4; j++)
            #pragma unroll
            for (int k = 0; k < 4; k++) acc[i][j][k] = 0.f;

    LOAD_A(0); LOAD_B(0);
    STORE_AB(0);
    if (NCH > 1) { LOAD_A(1); LOAD_B(1); }
    __syncthreads();

    for (int ch = 0; ch < NCH; ch++) {
        int cur = ch & 1;
        if (ch + 1 < NCH) STORE_AB(cur ^ 1);
        if (ch + 2 < NCH) { LOAD_A(ch + 2); LOAD_B(ch + 2); }

        const float* As_ = sm + cur * STG_FLOATS;
        const float* Bs_ = As_ + 4096;
        #pragma unroll
        for (int kb = 0; kb < 4; kb++) {
            float4 af[4]; float2 bf[4];
            #pragma unroll
            for (int mt = 0; mt < 4; mt++)
                af[mt] = *(const float4*)(As_ + (wm * 4 + mt) * 512 + kb * 128 + lane * 4);
            #pragma unroll
            for (int nt = 0; nt < 4; nt++)
                bf[nt] = *(const float2*)(Bs_ + (wn * 4 + nt) * 264 + kb * 64 + lane * 2);
            #pragma unroll
            for (int mt = 0; mt < 4; mt++)
                #pragma unroll
                for (int nt = 0; nt < 4; nt++)
                    mma_tf32(acc[mt][nt], af[mt], bf[nt]);
        }
        __syncthreads();
    }

    #undef LOAD_A
    #undef LOAD_B
    #undef STORE_AB
    #undef CVF

    const int g = lane >> 2, tg = lane & 3;
    #pragma unroll
    for (int mt = 0; mt < 4; mt++) {
        int m = m0 + wm * 64 + mt * 16 + g;
        float bs0 = 0.f, bs1 = 0.f;
        if (MODE != 2) { bs0 = bias[m]; bs1 = bias[m + 8]; }
        #pragma unroll
        for (int nt = 0; nt < 4; nt++) {
            int n = n0 + wn * 32 + nt * 8 + tg * 2;
            if (MODE == 0) {
                size_t base0 = (size_t)(bb * CC + m) * NP + n;
                size_t base1 = base0 + (size_t)8 * NP;
                *(float2*)(g_y + base0) = make_float2(acc[mt][nt][0] + bs0, acc[mt][nt][1] + bs0);
                *(float2*)(g_y + base1) = make_float2(acc[mt][nt][2] + bs1, acc[mt][nt][3] + bs1);
            } else if (MODE == 1) {
                size_t base0 = (size_t)(bb * CC + m) * NP + n;
                size_t base1 = base0 + (size_t)8 * NP;
                *(uint32_t*)(g_vh + base0) = pbf2(acc[mt][nt][0] + bs0, acc[mt][nt][1] + bs0);
                *(uint32_t*)(g_vh + base1) = pbf2(acc[mt][nt][2] + bs1, acc[mt][nt][3] + bs1);
            } else {
                size_t base0 = ((size_t)bb * NP + m) * NP + n;
                size_t base1 = base0 + (size_t)8 * NP;
                *(uint32_t*)(g_attnh + base0) = pbf2(acc[mt][nt][0], acc[mt][nt][1]);
                *(uint32_t*)(g_attnh + base1) = pbf2(acc[mt][nt][2], acc[mt][nt][3]);
            }
        }
    }
}

// ============================================================================
// o-GEMM, bf16 m16n8k16: o[c,i] = sum_j v[c,j]*attnh[i,j]; dout = gamma*o+g_out
// ============================================================================
#define OA_U32 2048
#define OB_U32 (16*136)
#define OSTG_U32 (OA_U32 + OB_U32)
#define OSMEM (2 * OSTG_U32 * 4)

__global__ __launch_bounds__(256, 1)
void o_gemm_bf16(const float* __restrict__ gamma, float* __restrict__ dout) {
    extern __shared__ uint32_t smu[];
    const int tid = threadIdx.x, wid = tid >> 5, lane = tid & 31;
    const int bb = blockIdx.z, m0 = blockIdx.y * 128, i0 = blockIdx.x * 128;
    const int wm = wid & 1, wn = wid >> 1;

    const uint32_t *av0 = nullptr, *av1 = nullptr;
    uint32_t aoff = 0;
    if (tid < 128) {
        int rpi = tid >> 1, akb = tid & 1;
        int mt = rpi >> 3, rp = rpi & 7;
        int m = m0 + mt * 16 + rp;
        av0 = (const uint32_t*)(g_vh + (size_t)(bb * CC + m) * NP) + akb * 8;
        av1 = av0 + (size_t)4 * NP;
        aoff = mt * 256 + akb * 128 + rp * 16;
    }
    const int bn = tid >> 1, bkb = tid & 1;
    const __nv_bfloat16* bptr = g_attnh + ((size_t)bb * NP + i0 + bn) * NP + bkb * 16;
    const uint32_t boff = OA_U32 + (bn >> 3) * 136 + bkb * 68 + (bn & 7) * 8;

    uint32_t a0u[8], a1u[8];
    uint32_t brg[8];

    #define OLOAD(ch_) do { \
        if (tid < 128) { \
            *(uint4*)(a0u)     = *(const uint4*)(av0 + (size_t)(ch_) * 16); \
            *(uint4*)(a0u + 4) = *(const uint4*)(av0 + (size_t)(ch_) * 16 + 4); \
            *(uint4*)(a1u)     = *(const uint4*)(av1 + (size_t)(ch_) * 16); \
            *(uint4*)(a1u + 4) = *(const uint4*)(av1 + (size_t)(ch_) * 16 + 4); \
        } \
        *(uint4*)(brg)     = *(const uint4*)(bptr + (size_t)(ch_) * 32); \
        *(uint4*)(brg + 4) = *(const uint4*)(bptr + (size_t)(ch_) * 32 + 8); \
    } while (0)

    #define OSTORE(stg_) do { \
        uint32_t* s_ = smu + (stg_) * OSTG_U32; \
        if (tid < 128) { \
            _Pragma("unroll") \
            for (int t = 0; t < 4; t++) { \
                *(uint4*)(s_ + aoff + t * 4) = \
                    make_uint4(a0u[t], a1u[t], a0u[t + 4], a1u[t + 4]); \
            } \
        } \
        _Pragma("unroll") \
        for (int t = 0; t < 4; t++) \
            *(uint2*)(s_ + boff + t * 2) = make_uint2(brg[t], brg[t + 4]); \
    } while (0)

    float acc[4][4][4];
    #pragma unroll
    for (int i = 0; i < 4; i++)
        #pragma unroll
        for (int j = 0; j < 4; j++)
            #pragma unroll
            for (int k = 0; k < 4; k++) acc[i][j][k] = 0.f;

    OLOAD(0); OSTORE(0); OLOAD(1);
    __syncthreads();

    constexpr int NCH = NP / 32;   // 128
    for (int ch = 0; ch < NCH; ch++) {
        int cur = ch & 1;
        if (ch + 1 < NCH) OSTORE(cur ^ 1);
        if (ch + 2 < NCH) OLOAD(ch + 2);

        const uint32_t* s_ = smu + cur * OSTG_U32;
        #pragma unroll
        for (int kb = 0; kb < 2; kb++) {
            uint4 af[4]; uint2 bf[4];
            #pragma unroll
            for (int mt = 0; mt < 4; mt++)
                af[mt] = *(const uint4*)(s_ + (wm * 4 + mt) * 256 + kb * 128 + lane * 4);
            #pragma unroll
            for (int nt = 0; nt < 4; nt++)
                bf[nt] = *(const uint2*)(s_ + OA_U32 + (wn * 4 + nt) * 136 + kb * 68 + lane * 2);
            #pragma unroll
            for (int mt = 0; mt < 4; mt++)
                #pragma unroll
                for (int nt = 0; nt < 4; nt++)
                    mma_bf16(acc[mt][nt], af[mt], bf[nt]);
        }
        __syncthreads();
    }

    #undef OLOAD
    #undef OSTORE

    const int g = lane >> 2, tg = lane & 3;
    const float gm = gamma[0];
    #pragma unroll
    for (int mt = 0; mt < 4; mt++) {
        int m = m0 + wm * 64 + mt * 16 + g;
        #pragma unroll
        for (int nt = 0; nt < 4; nt++) {
            int n = i0 + wn * 32 + nt * 8 + tg * 2;
            size_t base0 = (size_t)(bb * CC + m) * NP + n;
            size_t base1 = base0 + (size_t)8 * NP;
            const float* r0 = g_out + base0;
            const float* r1 = g_out + base1;
            *(float2*)(dout + base0) =
                make_float2(gm * acc[mt][nt][0] + r0[0], gm * acc[mt][nt][1] + r0[1]);
            *(float2*)(dout + base1) =
                make_float2(gm * acc[mt][nt][2] + r1[0], gm * acc[mt][nt][3] + r1[1]);
        }
    }
}

// ---------------- q and k projections fused (FFMA); outputs tf32 pre-rounded ----------------
__global__ __launch_bounds__(256) void qk_gemm(const float* __restrict__ wq, const float* __restrict__ bq,
                                               const float* __restrict__ wk, const float* __restrict__ bk) {
    __shared__ float As[8][64];
    __shared__ float Bs[8][128];
    int tid = threadIdx.x, b = blockIdx.z;
    int p0 = blockIdx.x * 128;
    int arow = tid >> 2;
    int acol = (tid & 3) * 2;
    const float* ap = ((arow < 32) ? (wq + arow * CC) : (wk + (arow - 32) * CC)) + acol;
    int brow = tid >> 5, bcol = (tid & 31) * 4;
    const float* bp = g_out + (b * CC + brow) * NP + p0 + bcol;
    int ty = tid >> 4, tx = tid & 15;
    float acc[4][8];
    #pragma unroll
    for (int i = 0; i < 4; i++)
        #pragma unroll
        for (int j = 0; j < 8; j++) acc[i][j] = 0.f;

    for (int it = 0; it < CC / 8; ++it) {
        float2 av = *(const float2*)(ap + it * 8);
        float4 bv = *(const float4*)(bp + (size_t)it * 8 * NP);
        __syncthreads();
        As[acol + 0][arow] = av.x;
        As[acol + 1][arow] = av.y;
        *(float4*)&Bs[brow][bcol] = bv;
        __syncthreads();
        #pragma unroll
        for (int kk = 0; kk < 8; kk++) {
            float a[4], bvv[8];
            float4 t0 = *(const float4*)&As[kk][ty * 4];
            a[0]=t0.x; a[1]=t0.y; a[2]=t0.z; a[3]=t0.w;
            float4 u0 = *(const float4*)&Bs[kk][tx * 8];
            float4 u1 = *(const float4*)&Bs[kk][tx * 8 + 4];
            bvv[0]=u0.x; bvv[1]=u0.y; bvv[2]=u0.z; bvv[3]=u0.w;
            bvv[4]=u1.x; bvv[5]=u1.y; bvv[6]=u1.z; bvv[7]=u1.w;
            #pragma unroll
            for (int i = 0; i < 4; i++)
                #pragma unroll
                for (int j = 0; j < 8; j++)
                    acc[i][j] += a[i] * bvv[j];
        }
    }
    #pragma unroll
    for (int i = 0; i < 4; i++) {
        int row = ty * 4 + i;
        float bias = (row < 32) ? bq[row] : bk[row - 32];
        float* dst = ((row < 32) ? (g_q + (b * C8 + row) * NP)
                                 : (g_k + (b * C8 + row - 32) * NP)) + p0 + tx * 8;
        *(float4*)dst = make_float4(tf32r(acc[i][0]+bias), tf32r(acc[i][1]+bias),
                                    tf32r(acc[i][2]+bias), tf32r(acc[i][3]+bias));
        *(float4*)(dst + 4) = make_float4(tf32r(acc[i][4]+bias), tf32r(acc[i][5]+bias),
                                          tf32r(acc[i][6]+bias), tf32r(acc[i][7]+bias));
    }
}

// ---------------- row softmax over 4096, bf16 in place (u32-vectorized) ----------------
__global__ __launch_bounds__(256) void softmax_kernel() {
    size_t row = blockIdx.x;
    uint32_t* ptr = (uint32_t*)(g_attnh + row * (size_t)NP);
    int tid = threadIdx.x;
    float vals[16];
    float m = -1e30f;
    #pragma unroll
    for (int s = 0; s < 8; s++) {
        uint32_t u = ptr[tid + s * 256];
        float lo = __bfloat162float(__ushort_as_bfloat16((unsigned short)(u & 0xffff)));
        float hi = __bfloat162float(__ushort_as_bfloat16((unsigned short)(u >> 16)));
        vals[2 * s] = lo; vals[2 * s + 1] = hi;
        m = fmaxf(m, fmaxf(lo, hi));
    }
    #pragma unroll
    for (int o = 16; o; o >>= 1) m = fmaxf(m, __shfl_xor_sync(0xffffffffu, m, o));
    __shared__ float shm[8], shs[8];
    int w = tid >> 5, l = tid & 31;
    if (l == 0) shm[w] = m;
    __syncthreads();
    m = fmaxf(fmaxf(fmaxf(shm[0], shm[1]), fmaxf(shm[2], shm[3])),
              fmaxf(fmaxf(shm[4], shm[5]), fmaxf(shm[6], shm[7])));
    float sum = 0.f;
    #pragma unroll
    for (int s = 0; s < 16; s++) {
        vals[s] = __expf(vals[s] - m);
        sum += vals[s];
    }
    #pragma unroll
    for (int o = 16; o; o >>= 1) sum += __shfl_xor_sync(0xffffffffu, sum, o);
    if (l == 0) shs[w] = sum;
    __syncthreads();
    sum = shs[0] + shs[1] + shs[2] + shs[3] + shs[4] + shs[5] + shs[6] + shs[7];
    float inv = 1.0f / sum;
    #pragma unroll
    for (int s = 0; s < 8; s++)
        ptr[tid + s * 256] = pbf2(vals[2 * s] * inv, vals[2 * s + 1] * inv);
}

// ---------------- launcher: forked-stream capture graph ----------------
extern "C" void kernel_launch(void* const* d_in, const int* in_sizes, int n_in,
                              void* d_out, int out_size) {
    const float* x     = (const float*)d_in[0];
    const float* w1    = (const float*)d_in[1];
    const float* b1    = (const float*)d_in[2];
    const float* w2    = (const float*)d_in[3];
    const float* b2    = (const float*)d_in[4];
    const float* wq    = (const float*)d_in[5];
    const float* bq    = (const float*)d_in[6];
    const float* wk    = (const float*)d_in[7];
    const float* bk    = (const float*)d_in[8];
    const float* wv    = (const float*)d_in[9];
    const float* bv    = (const float*)d_in[10];
    const float* gamma = (const float*)d_in[11];
    float* out = (float*)d_out;

    cudaFuncSetAttribute(tc_gemm<0, KCONV, 0>, cudaFuncAttributeMaxDynamicSharedMemorySize, SMEM_DYN);
    cudaFuncSetAttribute(tc_gemm<0, KCONV, 1>, cudaFuncAttributeMaxDynamicSharedMemorySize, SMEM_DYN);
    cudaFuncSetAttribute(tc_gemm<1, CC, 0>,    cudaFuncAttributeMaxDynamicSharedMemorySize, SMEM_DYN);
    cudaFuncSetAttribute(tc_gemm<2, C8, 0>,    cudaFuncAttributeMaxDynamicSharedMemorySize, SMEM_DYN);
    cudaFuncSetAttribute(o_gemm_bf16,          cudaFuncAttributeMaxDynamicSharedMemorySize, OSMEM);

    // Side stream (created per call, never destroyed: destroying a stream in an
    // active capture invalidates the capture).
    cudaStream_t s1;
    cudaStreamCreateWithFlags(&s1, cudaStreamNonBlocking);
    cudaEvent_t evA, evB, evC, evD;
    cudaEventCreateWithFlags(&evA, cudaEventDisableTiming);
    cudaEventCreateWithFlags(&evB, cudaEventDisableTiming);
    cudaEventCreateWithFlags(&evC, cudaEventDisableTiming);
    cudaEventCreateWithFlags(&evD, cudaEventDisableTiming);

    dim3 g128(NP / 128, CC / 128, BB);   // (32,2,2)

    // fork: wtrans on s1 overlaps pad on main stream
    cudaEventRecord(evA, 0);
    cudaStreamWaitEvent(s1, evA, 0);
    wtrans_kernel<<<dim3(CC, 2), 256, 0, s1>>>(w1, w2);
    pad_kernel<<<BB * CC, 256>>>(x);
    cudaEventRecord(evB, s1);
    cudaStreamWaitEvent(0, evB, 0);

    // conv chain (serial by data dependence)
    tc_gemm<0, KCONV, 0><<<g128, 256, SMEM_DYN>>>(nullptr, b1);
    stats_pad_kernel<<<BB * CC, 256>>>();
    tc_gemm<0, KCONV, 1><<<g128, 256, SMEM_DYN>>>(nullptr, b2);
    stats_norm_kernel<<<BB * CC, 256>>>(x);

    // fork: v-projection (s1) overlaps qk -> energy -> softmax (main)
    cudaEventRecord(evC, 0);
    cudaStreamWaitEvent(s1, evC, 0);
    tc_gemm<1, CC, 0><<<g128, 256, SMEM_DYN, s1>>>(wv, bv);
    qk_gemm<<<dim3(NP / 128, 1, BB), 256>>>(wq, bq, wk, bk);
    tc_gemm<2, C8, 0><<<dim3(NP / 128, NP / 128, BB), 256, SMEM_DYN>>>(nullptr, nullptr);  // energy
    softmax_kernel<<<BB * NP, 256>>>();
    cudaEventRecord(evD, s1);
    cudaStreamWaitEvent(0, evD, 0);

    // join: o-GEMM needs both g_vh (s1) and g_attnh (main)
    o_gemm_bf16<<<g128, 256, OSMEM>>>(gamma, out);
}